// round 1
// baseline (speedup 1.0000x reference)
#include <cuda_runtime.h>
#include <cuda_bf16.h>
#include <math.h>

// Problem constants
#define B_   16
#define L_   256
#define LQ_  64
#define ET_  128
#define H_   4
#define ETK_ 32
#define DIM_ 64      // 2*D_IN
#define D_IN_ 32
#define IE_  8       // INIT_EMBED

// ---------------- scratch (device globals; no allocation) ----------------
__device__ float g_q[H_ * LQ_ * ETK_];           // (h, q, e)
__device__ float g_k[B_ * H_ * L_ * ETK_];       // (b, h, l, e)
__device__ float g_att[B_ * LQ_ * (H_ * DIM_)];  // (b, q, h*64+d)
__device__ float g_Wc[2 * ET_ * ET_];            // 256 x 128 : Wo @ W_ih
__device__ float g_bc[ET_];                      // combined bias
__device__ float g_pre[B_ * LQ_ * ET_];          // (b, t, j)

// ======================================================================
// Kernel A: time embedding + Q/K projections.
// rows 0..4095 -> K rows (b*L + l), rows 4096..4159 -> Q rows.
// grid 130 blocks of 32 rows, 256 threads, 4x4 register tile.
// ======================================================================
__global__ void embed_proj_kernel(
    const float* __restrict__ times, const float* __restrict__ query,
    const float* __restrict__ w_lin, const float* __restrict__ b_lin,
    const float* __restrict__ w_per, const float* __restrict__ b_per,
    const float* __restrict__ Wk, const float* __restrict__ bk,
    const float* __restrict__ Wq, const float* __restrict__ bq)
{
    __shared__ float emb[32 * 128];
    __shared__ float tv[32];

    const int tid = threadIdx.x;
    const bool is_q = (blockIdx.x >= 128);
    const int row0 = blockIdx.x * 32;

    if (tid < 32) tv[tid] = is_q ? query[row0 - 4096 + tid] : times[row0 + tid];
    __syncthreads();

    const float wl = w_lin[0], bl = b_lin[0];
    for (int idx = tid; idx < 32 * 128; idx += 256) {
        int r = idx >> 7, c = idx & 127;
        float t = tv[r];
        emb[idx] = (c == 0) ? fmaf(t, wl, bl)
                            : sinf(fmaf(t, w_per[c - 1], b_per[c - 1]));
    }
    __syncthreads();

    const float* W    = is_q ? Wq : Wk;
    const float* bias = is_q ? bq : bk;

    const int tx = tid & 31;   // col group: cols 4*tx .. 4*tx+3
    const int ty = tid >> 5;   // row group: rows 4*ty .. 4*ty+3

    float acc[4][4];
#pragma unroll
    for (int r = 0; r < 4; r++)
#pragma unroll
        for (int c = 0; c < 4; c++) acc[r][c] = 0.f;

    for (int k2 = 0; k2 < 128; k2++) {
        float4 wv = *(const float4*)(W + k2 * 128 + 4 * tx);
#pragma unroll
        for (int r = 0; r < 4; r++) {
            float e = emb[(4 * ty + r) * 128 + k2];
            acc[r][0] = fmaf(e, wv.x, acc[r][0]);
            acc[r][1] = fmaf(e, wv.y, acc[r][1]);
            acc[r][2] = fmaf(e, wv.z, acc[r][2]);
            acc[r][3] = fmaf(e, wv.w, acc[r][3]);
        }
    }

#pragma unroll
    for (int r = 0; r < 4; r++) {
        int grow = row0 + 4 * ty + r;
#pragma unroll
        for (int c = 0; c < 4; c++) {
            int col = 4 * tx + c;
            float v = acc[r][c] + bias[col];
            int h = col >> 5, e = col & 31;
            if (is_q) {
                int qi = grow - 4096;
                g_q[(h * LQ_ + qi) * ETK_ + e] = v;
            } else {
                int b = grow >> 8, l = grow & 255;
                g_k[((b * H_ + h) * L_ + l) * ETK_ + e] = v;
            }
        }
    }
}

// ======================================================================
// Kernel B: masked per-feature attention.
// grid (qt=4, h=4, b=16), 512 threads. dynamic smem = 83968 B.
//   att[b,h,q,d]      = sum_k e_k*m[k,d]*x[k,d] / sum_k e_k*m[k,d]
//   att[b,h,q,32+d]   = 1.0  (xc second half == mask; ratio is exactly 1)
// ======================================================================
__global__ void attn_kernel(const float* __restrict__ x,
                            const float* __restrict__ mask)
{
    extern __shared__ float smem[];
    float*  qv  = smem;                         // 16*32
    float*  s_s = smem + 512;                   // 16*256 (scores, then exp)
    float2* mxm = (float2*)(smem + 512 + 4096); // 256*32 : (mask*x, mask)

    const int tid = threadIdx.x;
    const int qt = blockIdx.x, h = blockIdx.y, b = blockIdx.z;

    // load q vectors for this tile (contiguous)
    qv[tid] = g_q[(h * LQ_ + qt * 16) * ETK_ + tid];

    // load mask*x / mask for batch b
    const float* xb = x    + b * L_ * D_IN_;
    const float* mb = mask + b * L_ * D_IN_;
    for (int idx = tid; idx < L_ * D_IN_; idx += 512) {
        float m = mb[idx];
        mxm[idx] = make_float2(m * xb[idx], m);
    }
    __syncthreads();

    // scores: thread -> key k, 8 queries each
    {
        const int k  = tid & 255;
        const int qh = tid >> 8;
        const float* kp = g_k + ((b * H_ + h) * L_ + k) * ETK_;
        float kv[32];
#pragma unroll
        for (int i = 0; i < 8; i++) {
            float4 v = *(const float4*)(kp + 4 * i);
            kv[4 * i] = v.x; kv[4 * i + 1] = v.y; kv[4 * i + 2] = v.z; kv[4 * i + 3] = v.w;
        }
#pragma unroll
        for (int qq = 0; qq < 8; qq++) {
            int q = qh * 8 + qq;
            float acc = 0.f;
#pragma unroll
            for (int e = 0; e < 32; e++) acc = fmaf(qv[q * 32 + e], kv[e], acc);
            s_s[q * 256 + k] = acc * 0.17677669529663687f; // 1/sqrt(32)
        }
    }
    __syncthreads();

    // row max + exp (warp w handles query q=w; 16 warps)
    {
        const int wq = tid >> 5, lane = tid & 31;
        float vals[8], m = -1e30f;
#pragma unroll
        for (int i = 0; i < 8; i++) {
            vals[i] = s_s[wq * 256 + lane + 32 * i];
            m = fmaxf(m, vals[i]);
        }
#pragma unroll
        for (int off = 16; off; off >>= 1)
            m = fmaxf(m, __shfl_xor_sync(0xffffffffu, m, off));
#pragma unroll
        for (int i = 0; i < 8; i++)
            s_s[wq * 256 + lane + 32 * i] = expf(vals[i] - m);
    }
    __syncthreads();

    // num/den: thread -> (q = tid>>5, d = tid&31)
    {
        const int q = tid >> 5, d = tid & 31;
        float num = 0.f, den = 0.f;
        const float* ep = s_s + q * 256;
        const float2* vp = mxm + d;
#pragma unroll 4
        for (int k = 0; k < 256; k++) {
            float  e = ep[k];
            float2 v = vp[k * 32];
            num = fmaf(e, v.x, num);
            den = fmaf(e, v.y, den);
        }
        float att = (den > 0.f) ? (num / den) : 0.f;
        int base = (b * LQ_ + qt * 16 + q) * (H_ * DIM_) + h * DIM_;
        g_att[base + d]      = att;
        g_att[base + 32 + d] = 1.0f;
    }
}

// ======================================================================
// Kernel C: combined weight Wc = Wo @ W_ih (256x128), bc = bo@W_ih+b_ih+b_hh.
// grid 257 x 128 threads.
// ======================================================================
__global__ void combine_w_kernel(const float* __restrict__ Wo,
                                 const float* __restrict__ bo,
                                 const float* __restrict__ W_ih,
                                 const float* __restrict__ b_ih,
                                 const float* __restrict__ b_hh)
{
    __shared__ float row_s[128];
    const int j = threadIdx.x;
    if (blockIdx.x < 256) {
        row_s[j] = Wo[blockIdx.x * 128 + j];
        __syncthreads();
        float acc = 0.f;
#pragma unroll 8
        for (int m = 0; m < 128; m++) acc = fmaf(row_s[m], W_ih[m * 128 + j], acc);
        g_Wc[blockIdx.x * 128 + j] = acc;
    } else {
        row_s[j] = bo[j];
        __syncthreads();
        float acc = b_ih[j] + b_hh[j];
#pragma unroll 8
        for (int m = 0; m < 128; m++) acc = fmaf(row_s[m], W_ih[m * 128 + j], acc);
        g_bc[j] = acc;
    }
}

// ======================================================================
// Kernel D: pre = att @ Wc + bc   (1024 x 128, K=256)
// grid 64 blocks of 16 rows, 256 threads, 2x4 register tile.
// ======================================================================
__global__ void pre_kernel()
{
    __shared__ float a_s[16 * 256];
    const int tid = threadIdx.x;
    const int r0 = blockIdx.x * 16;

    for (int idx = tid; idx < 16 * 256; idx += 256)
        a_s[idx] = g_att[r0 * 256 + idx];
    __syncthreads();

    const int tx = tid & 31;   // cols 4*tx..
    const int ty = tid >> 5;   // rows 2*ty, 2*ty+1

    float acc[2][4];
#pragma unroll
    for (int r = 0; r < 2; r++)
#pragma unroll
        for (int c = 0; c < 4; c++) acc[r][c] = 0.f;

    for (int i = 0; i < 256; i++) {
        float4 w = *(const float4*)(g_Wc + i * 128 + 4 * tx);
        float e0 = a_s[(2 * ty) * 256 + i];
        float e1 = a_s[(2 * ty + 1) * 256 + i];
        acc[0][0] = fmaf(e0, w.x, acc[0][0]); acc[0][1] = fmaf(e0, w.y, acc[0][1]);
        acc[0][2] = fmaf(e0, w.z, acc[0][2]); acc[0][3] = fmaf(e0, w.w, acc[0][3]);
        acc[1][0] = fmaf(e1, w.x, acc[1][0]); acc[1][1] = fmaf(e1, w.y, acc[1][1]);
        acc[1][2] = fmaf(e1, w.z, acc[1][2]); acc[1][3] = fmaf(e1, w.w, acc[1][3]);
    }

#pragma unroll
    for (int r = 0; r < 2; r++) {
        int row = r0 + 2 * ty + r;
#pragma unroll
        for (int c = 0; c < 4; c++) {
            int col = 4 * tx + c;
            g_pre[row * 128 + col] = acc[r][c] + g_bc[col];
        }
    }
}

// ======================================================================
// Kernel E: RNN (64 sequential steps) + regressor, fused. grid 16 x 512.
// thread (j = tid&127, s = tid>>7); W_hh column slice in registers.
// ======================================================================
__device__ __forceinline__ void matvec128(const float* in_s, float* out_s,
                                          const float* __restrict__ Wg,
                                          const float* __restrict__ bg,
                                          int s, int j, int tid,
                                          float part[4][128])
{
    float a0 = 0.f, a1 = 0.f;
    const float* wp = Wg + (32 * s) * 128 + j;
#pragma unroll
    for (int i = 0; i < 32; i += 2) {
        a0 = fmaf(in_s[32 * s + i],     wp[i * 128],       a0);
        a1 = fmaf(in_s[32 * s + i + 1], wp[(i + 1) * 128], a1);
    }
    part[s][j] = a0 + a1;
    __syncthreads();
    if (tid < 128)
        out_s[tid] = bg[tid] + ((part[0][tid] + part[1][tid]) +
                                (part[2][tid] + part[3][tid]));
    __syncthreads();
}

__global__ void rnn_regr_kernel(const float* __restrict__ W_hh,
                                const float* __restrict__ r1_w, const float* __restrict__ r1_b,
                                const float* __restrict__ r2_w, const float* __restrict__ r2_b,
                                const float* __restrict__ r3_w, const float* __restrict__ r3_b,
                                const float* __restrict__ r4_w, const float* __restrict__ r4_b,
                                float* __restrict__ out)
{
    __shared__ float h_s[128];
    __shared__ float v_s[128];
    __shared__ float part[4][128];

    const int tid = threadIdx.x;
    const int j = tid & 127;
    const int s = tid >> 7;

    float w[32];
#pragma unroll
    for (int i = 0; i < 32; i++) w[i] = W_hh[(32 * s + i) * 128 + j];

    if (tid < 128) h_s[tid] = 0.f;
    __syncthreads();

    const float* pre_b = g_pre + blockIdx.x * LQ_ * ET_;

    for (int step = 0; step < LQ_; step++) {
        float a0 = 0.f, a1 = 0.f, a2 = 0.f, a3 = 0.f;
#pragma unroll
        for (int i = 0; i < 32; i += 4) {
            a0 = fmaf(h_s[32 * s + i],     w[i],     a0);
            a1 = fmaf(h_s[32 * s + i + 1], w[i + 1], a1);
            a2 = fmaf(h_s[32 * s + i + 2], w[i + 2], a2);
            a3 = fmaf(h_s[32 * s + i + 3], w[i + 3], a3);
        }
        part[s][j] = (a0 + a1) + (a2 + a3);
        __syncthreads();
        if (tid < 128) {
            float hn = tanhf(pre_b[step * 128 + tid] +
                             ((part[0][tid] + part[1][tid]) +
                              (part[2][tid] + part[3][tid])));
            h_s[tid] = hn;
        }
        __syncthreads();
    }

    // regressor: h -> 128 -> 128 -> 128 -> 8 (no activations)
    matvec128(h_s, v_s, r1_w, r1_b, s, j, tid, part);
    matvec128(v_s, h_s, r2_w, r2_b, s, j, tid, part);
    matvec128(h_s, v_s, r3_w, r3_b, s, j, tid, part);

    if (tid < 256) {
        int o = tid >> 5, lane = tid & 31;
        float acc = 0.f;
#pragma unroll
        for (int ii = 0; ii < 4; ii++) {
            int i = lane * 4 + ii;
            acc = fmaf(v_s[i], r4_w[i * 8 + o], acc);
        }
#pragma unroll
        for (int off = 16; off; off >>= 1)
            acc += __shfl_xor_sync(0xffffffffu, acc, off);
        if (lane == 0) out[blockIdx.x * 8 + o] = acc + r4_b[o];
    }
}

// ======================================================================
extern "C" void kernel_launch(void* const* d_in, const int* in_sizes, int n_in,
                              void* d_out, int out_size)
{
    const float* x     = (const float*)d_in[0];
    const float* times = (const float*)d_in[1];
    const float* mask  = (const float*)d_in[2];
    const float* query = (const float*)d_in[3];
    const float* w_lin = (const float*)d_in[4];
    const float* b_lin = (const float*)d_in[5];
    const float* w_per = (const float*)d_in[6];
    const float* b_per = (const float*)d_in[7];
    const float* Wq    = (const float*)d_in[8];
    const float* bq    = (const float*)d_in[9];
    const float* Wk    = (const float*)d_in[10];
    const float* bk    = (const float*)d_in[11];
    const float* Wo    = (const float*)d_in[12];
    const float* bo    = (const float*)d_in[13];
    const float* W_ih  = (const float*)d_in[14];
    const float* b_ih  = (const float*)d_in[15];
    const float* W_hh  = (const float*)d_in[16];
    const float* b_hh  = (const float*)d_in[17];
    const float* r1_w  = (const float*)d_in[18];
    const float* r1_b  = (const float*)d_in[19];
    const float* r2_w  = (const float*)d_in[20];
    const float* r2_b  = (const float*)d_in[21];
    const float* r3_w  = (const float*)d_in[22];
    const float* r3_b  = (const float*)d_in[23];
    const float* r4_w  = (const float*)d_in[24];
    const float* r4_b  = (const float*)d_in[25];
    float* out = (float*)d_out;

    embed_proj_kernel<<<130, 256>>>(times, query, w_lin, b_lin, w_per, b_per,
                                    Wk, bk, Wq, bq);

    const int ATTN_SMEM = (512 + 4096) * 4 + 256 * 32 * 8; // 83968 B
    cudaFuncSetAttribute(attn_kernel,
                         cudaFuncAttributeMaxDynamicSharedMemorySize, ATTN_SMEM);
    attn_kernel<<<dim3(4, 4, 16), 512, ATTN_SMEM>>>(x, mask);

    combine_w_kernel<<<257, 128>>>(Wo, bo, W_ih, b_ih, b_hh);

    pre_kernel<<<64, 256>>>();

    rnn_regr_kernel<<<16, 512>>>(W_hh, r1_w, r1_b, r2_w, r2_b,
                                 r3_w, r3_b, r4_w, r4_b, out);
}

// round 2
// speedup vs baseline: 1.4541x; 1.4541x over previous
#include <cuda_runtime.h>
#include <cuda_bf16.h>
#include <math.h>

// Problem constants
#define B_   16
#define L_   256
#define LQ_  64
#define ET_  128
#define H_   4
#define ETK_ 32
#define DIM_ 64      // 2*D_IN
#define D_IN_ 32
#define IE_  8       // INIT_EMBED

// ---------------- scratch (device globals; no allocation) ----------------
__device__ float g_q[H_ * LQ_ * ETK_];           // (h, q, e)
__device__ float g_k[B_ * H_ * L_ * ETK_];       // (b, h, l, e)
__device__ float g_att[B_ * LQ_ * (H_ * DIM_)];  // (b, q, h*64+d)
__device__ float g_Wc[2 * ET_ * ET_];            // 256 x 128 : Wo @ W_ih
__device__ float g_bc[ET_];                      // combined bias
__device__ float g_pre[B_ * LQ_ * ET_];          // (b, t, j)

// ======================================================================
// Kernel A: time embedding + Q/K projections, W staged through smem.
// rows 0..4095 -> K rows (b*L + l), rows 4096..4159 -> Q rows.
// grid 130 blocks of 32 rows, 256 threads, 4x4 register tile.
// ======================================================================
__global__ void embed_proj_kernel(
    const float* __restrict__ times, const float* __restrict__ query,
    const float* __restrict__ w_lin, const float* __restrict__ b_lin,
    const float* __restrict__ w_per, const float* __restrict__ b_per,
    const float* __restrict__ Wk, const float* __restrict__ bk,
    const float* __restrict__ Wq, const float* __restrict__ bq)
{
    __shared__ float emb[32 * 128];
    __shared__ float w_s[32 * 128];
    __shared__ float tv[32];

    const int tid = threadIdx.x;
    const bool is_q = (blockIdx.x >= 128);
    const int row0 = blockIdx.x * 32;

    if (tid < 32) tv[tid] = is_q ? query[row0 - 4096 + tid] : times[row0 + tid];
    __syncthreads();

    const float wl = w_lin[0], bl = b_lin[0];
    for (int idx = tid; idx < 32 * 128; idx += 256) {
        int r = idx >> 7, c = idx & 127;
        float t = tv[r];
        emb[idx] = (c == 0) ? fmaf(t, wl, bl)
                            : sinf(fmaf(t, w_per[c - 1], b_per[c - 1]));
    }

    const float* W    = is_q ? Wq : Wk;
    const float* bias = is_q ? bq : bk;

    const int tx = tid & 31;   // col group: cols 4*tx .. 4*tx+3
    const int ty = tid >> 5;   // row group: rows 4*ty .. 4*ty+3

    float acc[4][4];
#pragma unroll
    for (int r = 0; r < 4; r++)
#pragma unroll
        for (int c = 0; c < 4; c++) acc[r][c] = 0.f;

    for (int kc = 0; kc < 128; kc += 32) {
        __syncthreads();
#pragma unroll
        for (int idx = tid * 4; idx < 32 * 128; idx += 256 * 4)
            *(float4*)(w_s + idx) = *(const float4*)(W + kc * 128 + idx);
        __syncthreads();

#pragma unroll
        for (int i = 0; i < 32; i++) {
            float4 wv = *(const float4*)(w_s + i * 128 + 4 * tx);
#pragma unroll
            for (int r = 0; r < 4; r++) {
                float e = emb[(4 * ty + r) * 128 + kc + i];
                acc[r][0] = fmaf(e, wv.x, acc[r][0]);
                acc[r][1] = fmaf(e, wv.y, acc[r][1]);
                acc[r][2] = fmaf(e, wv.z, acc[r][2]);
                acc[r][3] = fmaf(e, wv.w, acc[r][3]);
            }
        }
    }

#pragma unroll
    for (int r = 0; r < 4; r++) {
        int grow = row0 + 4 * ty + r;
#pragma unroll
        for (int c = 0; c < 4; c++) {
            int col = 4 * tx + c;
            float v = acc[r][c] + bias[col];
            int h = col >> 5, e = col & 31;
            if (is_q) {
                int qi = grow - 4096;
                g_q[(h * LQ_ + qi) * ETK_ + e] = v;
            } else {
                int b = grow >> 8, l = grow & 255;
                g_k[((b * H_ + h) * L_ + l) * ETK_ + e] = v;
            }
        }
    }
}

// ======================================================================
// Kernel B: masked per-feature attention.
// grid (qt=4, h=4, b=16), 512 threads. dynamic smem = 83968 B.
//   att[b,h,q,d]      = sum_k e_k*m[k,d]*x[k,d] / sum_k e_k*m[k,d]
//   att[b,h,q,32+d]   = 1.0  (xc second half == mask; ratio is exactly 1)
// ======================================================================
__global__ void attn_kernel(const float* __restrict__ x,
                            const float* __restrict__ mask)
{
    extern __shared__ float smem[];
    float*  qv  = smem;                         // 16*32
    float*  s_s = smem + 512;                   // 16*256 (scores, then exp)
    float2* mxm = (float2*)(smem + 512 + 4096); // 256*32 : (mask*x, mask)

    const int tid = threadIdx.x;
    const int qt = blockIdx.x, h = blockIdx.y, b = blockIdx.z;

    // load q vectors for this tile (contiguous)
    qv[tid] = g_q[(h * LQ_ + qt * 16) * ETK_ + tid];

    // load mask*x / mask for batch b
    const float* xb = x    + b * L_ * D_IN_;
    const float* mb = mask + b * L_ * D_IN_;
    for (int idx = tid; idx < L_ * D_IN_; idx += 512) {
        float m = mb[idx];
        mxm[idx] = make_float2(m * xb[idx], m);
    }
    __syncthreads();

    // scores: thread -> key k, 8 queries each
    {
        const int k  = tid & 255;
        const int qh = tid >> 8;
        const float* kp = g_k + ((b * H_ + h) * L_ + k) * ETK_;
        float kv[32];
#pragma unroll
        for (int i = 0; i < 8; i++) {
            float4 v = *(const float4*)(kp + 4 * i);
            kv[4 * i] = v.x; kv[4 * i + 1] = v.y; kv[4 * i + 2] = v.z; kv[4 * i + 3] = v.w;
        }
#pragma unroll
        for (int qq = 0; qq < 8; qq++) {
            int q = qh * 8 + qq;
            float acc = 0.f;
#pragma unroll
            for (int e = 0; e < 32; e++) acc = fmaf(qv[q * 32 + e], kv[e], acc);
            s_s[q * 256 + k] = acc * 0.17677669529663687f; // 1/sqrt(32)
        }
    }
    __syncthreads();

    // row max + exp (warp w handles query q=w; 16 warps)
    {
        const int wq = tid >> 5, lane = tid & 31;
        float vals[8], m = -1e30f;
#pragma unroll
        for (int i = 0; i < 8; i++) {
            vals[i] = s_s[wq * 256 + lane + 32 * i];
            m = fmaxf(m, vals[i]);
        }
#pragma unroll
        for (int off = 16; off; off >>= 1)
            m = fmaxf(m, __shfl_xor_sync(0xffffffffu, m, off));
#pragma unroll
        for (int i = 0; i < 8; i++)
            s_s[wq * 256 + lane + 32 * i] = expf(vals[i] - m);
    }
    __syncthreads();

    // num/den: thread -> (q = tid>>5, d = tid&31)
    {
        const int q = tid >> 5, d = tid & 31;
        float num = 0.f, den = 0.f;
        const float* ep = s_s + q * 256;
        const float2* vp = mxm + d;
#pragma unroll 4
        for (int k = 0; k < 256; k++) {
            float  e = ep[k];
            float2 v = vp[k * 32];
            num = fmaf(e, v.x, num);
            den = fmaf(e, v.y, den);
        }
        float att = (den > 0.f) ? (num / den) : 0.f;
        int base = (b * LQ_ + qt * 16 + q) * (H_ * DIM_) + h * DIM_;
        g_att[base + d]      = att;
        g_att[base + 32 + d] = 1.0f;
    }
}

// ======================================================================
// Kernel C: Wc = Wo @ W_ih (256x128) tiled; block 16 does the bias row:
//   bc = bo @ W_ih + b_ih + b_hh
// grid 17 blocks x 256 threads. W_ih staged through smem.
// ======================================================================
__global__ void combine_w_kernel(const float* __restrict__ Wo,
                                 const float* __restrict__ bo,
                                 const float* __restrict__ W_ih,
                                 const float* __restrict__ b_ih,
                                 const float* __restrict__ b_hh)
{
    __shared__ float a_s[16 * 128];
    __shared__ float w_s[32 * 128];

    const int tid = threadIdx.x;

    if (blockIdx.x < 16) {
        const int r0 = blockIdx.x * 16;
#pragma unroll
        for (int idx = tid * 4; idx < 16 * 128; idx += 256 * 4)
            *(float4*)(a_s + idx) = *(const float4*)(Wo + r0 * 128 + idx);

        const int tx = tid & 31;
        const int ty = tid >> 5;
        float acc[2][4];
#pragma unroll
        for (int r = 0; r < 2; r++)
#pragma unroll
            for (int c = 0; c < 4; c++) acc[r][c] = 0.f;

        for (int kc = 0; kc < 128; kc += 32) {
            __syncthreads();
#pragma unroll
            for (int idx = tid * 4; idx < 32 * 128; idx += 256 * 4)
                *(float4*)(w_s + idx) = *(const float4*)(W_ih + kc * 128 + idx);
            __syncthreads();

#pragma unroll
            for (int i = 0; i < 32; i++) {
                float4 w = *(const float4*)(w_s + i * 128 + 4 * tx);
                float e0 = a_s[(2 * ty) * 128 + kc + i];
                float e1 = a_s[(2 * ty + 1) * 128 + kc + i];
                acc[0][0] = fmaf(e0, w.x, acc[0][0]); acc[0][1] = fmaf(e0, w.y, acc[0][1]);
                acc[0][2] = fmaf(e0, w.z, acc[0][2]); acc[0][3] = fmaf(e0, w.w, acc[0][3]);
                acc[1][0] = fmaf(e1, w.x, acc[1][0]); acc[1][1] = fmaf(e1, w.y, acc[1][1]);
                acc[1][2] = fmaf(e1, w.z, acc[1][2]); acc[1][3] = fmaf(e1, w.w, acc[1][3]);
            }
        }

#pragma unroll
        for (int r = 0; r < 2; r++) {
            int row = r0 + 2 * ty + r;
#pragma unroll
            for (int c = 0; c < 4; c++)
                g_Wc[row * 128 + 4 * tx + c] = acc[r][c];
        }
    } else {
        // bias row: bc = bo @ W_ih + b_ih + b_hh
        if (tid < 128) a_s[tid] = bo[tid];
        float acc = 0.f;
        for (int kc = 0; kc < 128; kc += 32) {
            __syncthreads();
#pragma unroll
            for (int idx = tid * 4; idx < 32 * 128; idx += 256 * 4)
                *(float4*)(w_s + idx) = *(const float4*)(W_ih + kc * 128 + idx);
            __syncthreads();
            if (tid < 128) {
#pragma unroll
                for (int i = 0; i < 32; i++)
                    acc = fmaf(a_s[kc + i], w_s[i * 128 + tid], acc);
            }
        }
        if (tid < 128) g_bc[tid] = acc + b_ih[tid] + b_hh[tid];
    }
}

// ======================================================================
// Kernel D: pre = att @ Wc + bc   (1024 x 128, K=256), Wc staged in smem.
// grid 64 blocks of 16 rows, 256 threads, 2x4 register tile.
// ======================================================================
__global__ void pre_kernel()
{
    __shared__ float a_s[16 * 256];
    __shared__ float w_s[32 * 128];

    const int tid = threadIdx.x;
    const int r0 = blockIdx.x * 16;

#pragma unroll
    for (int idx = tid * 4; idx < 16 * 256; idx += 256 * 4)
        *(float4*)(a_s + idx) = *(const float4*)(g_att + r0 * 256 + idx);

    const int tx = tid & 31;   // cols 4*tx..
    const int ty = tid >> 5;   // rows 2*ty, 2*ty+1

    float acc[2][4];
#pragma unroll
    for (int r = 0; r < 2; r++)
#pragma unroll
        for (int c = 0; c < 4; c++) acc[r][c] = 0.f;

    for (int kc = 0; kc < 256; kc += 32) {
        __syncthreads();
#pragma unroll
        for (int idx = tid * 4; idx < 32 * 128; idx += 256 * 4)
            *(float4*)(w_s + idx) = *(const float4*)(g_Wc + kc * 128 + idx);
        __syncthreads();

#pragma unroll
        for (int i = 0; i < 32; i++) {
            float4 w = *(const float4*)(w_s + i * 128 + 4 * tx);
            float e0 = a_s[(2 * ty) * 256 + kc + i];
            float e1 = a_s[(2 * ty + 1) * 256 + kc + i];
            acc[0][0] = fmaf(e0, w.x, acc[0][0]); acc[0][1] = fmaf(e0, w.y, acc[0][1]);
            acc[0][2] = fmaf(e0, w.z, acc[0][2]); acc[0][3] = fmaf(e0, w.w, acc[0][3]);
            acc[1][0] = fmaf(e1, w.x, acc[1][0]); acc[1][1] = fmaf(e1, w.y, acc[1][1]);
            acc[1][2] = fmaf(e1, w.z, acc[1][2]); acc[1][3] = fmaf(e1, w.w, acc[1][3]);
        }
    }

#pragma unroll
    for (int r = 0; r < 2; r++) {
        int row = r0 + 2 * ty + r;
#pragma unroll
        for (int c = 0; c < 4; c++) {
            int col = 4 * tx + c;
            g_pre[row * 128 + col] = acc[r][c] + g_bc[col];
        }
    }
}

// ======================================================================
// Kernel E: RNN (64 sequential steps) + regressor, fused. grid 16 x 512.
// thread (j = tid&127, s = tid>>7); W_hh column slice in registers.
// Next-step pre row is prefetched to hide L2 latency.
// ======================================================================
__device__ __forceinline__ void matvec128(const float* in_s, float* out_s,
                                          const float* __restrict__ Wg,
                                          const float* __restrict__ bg,
                                          int s, int j, int tid,
                                          float part[4][128])
{
    float a0 = 0.f, a1 = 0.f;
    const float* wp = Wg + (32 * s) * 128 + j;
#pragma unroll
    for (int i = 0; i < 32; i += 2) {
        a0 = fmaf(in_s[32 * s + i],     wp[i * 128],       a0);
        a1 = fmaf(in_s[32 * s + i + 1], wp[(i + 1) * 128], a1);
    }
    part[s][j] = a0 + a1;
    __syncthreads();
    if (tid < 128)
        out_s[tid] = bg[tid] + ((part[0][tid] + part[1][tid]) +
                                (part[2][tid] + part[3][tid]));
    __syncthreads();
}

__global__ void rnn_regr_kernel(const float* __restrict__ W_hh,
                                const float* __restrict__ r1_w, const float* __restrict__ r1_b,
                                const float* __restrict__ r2_w, const float* __restrict__ r2_b,
                                const float* __restrict__ r3_w, const float* __restrict__ r3_b,
                                const float* __restrict__ r4_w, const float* __restrict__ r4_b,
                                float* __restrict__ out)
{
    __shared__ float h_s[128];
    __shared__ float v_s[128];
    __shared__ float part[4][128];

    const int tid = threadIdx.x;
    const int j = tid & 127;
    const int s = tid >> 7;

    float w[32];
#pragma unroll
    for (int i = 0; i < 32; i++) w[i] = W_hh[(32 * s + i) * 128 + j];

    if (tid < 128) h_s[tid] = 0.f;
    __syncthreads();

    const float* pre_b = g_pre + blockIdx.x * LQ_ * ET_;
    float pre_cur = (tid < 128) ? pre_b[tid] : 0.f;

    for (int step = 0; step < LQ_; step++) {
        // prefetch next step's pre row early
        float pre_nxt = 0.f;
        if (tid < 128 && step + 1 < LQ_) pre_nxt = pre_b[(step + 1) * 128 + tid];

        float a0 = 0.f, a1 = 0.f, a2 = 0.f, a3 = 0.f;
#pragma unroll
        for (int i = 0; i < 32; i += 4) {
            a0 = fmaf(h_s[32 * s + i],     w[i],     a0);
            a1 = fmaf(h_s[32 * s + i + 1], w[i + 1], a1);
            a2 = fmaf(h_s[32 * s + i + 2], w[i + 2], a2);
            a3 = fmaf(h_s[32 * s + i + 3], w[i + 3], a3);
        }
        part[s][j] = (a0 + a1) + (a2 + a3);
        __syncthreads();
        if (tid < 128) {
            float hn = tanhf(pre_cur +
                             ((part[0][tid] + part[1][tid]) +
                              (part[2][tid] + part[3][tid])));
            h_s[tid] = hn;
        }
        __syncthreads();
        pre_cur = pre_nxt;
    }

    // regressor: h -> 128 -> 128 -> 128 -> 8 (no activations)
    matvec128(h_s, v_s, r1_w, r1_b, s, j, tid, part);
    matvec128(v_s, h_s, r2_w, r2_b, s, j, tid, part);
    matvec128(h_s, v_s, r3_w, r3_b, s, j, tid, part);

    if (tid < 256) {
        int o = tid >> 5, lane = tid & 31;
        float acc = 0.f;
#pragma unroll
        for (int ii = 0; ii < 4; ii++) {
            int i = lane * 4 + ii;
            acc = fmaf(v_s[i], r4_w[i * 8 + o], acc);
        }
#pragma unroll
        for (int off = 16; off; off >>= 1)
            acc += __shfl_xor_sync(0xffffffffu, acc, off);
        if (lane == 0) out[blockIdx.x * 8 + o] = acc + r4_b[o];
    }
}

// ======================================================================
extern "C" void kernel_launch(void* const* d_in, const int* in_sizes, int n_in,
                              void* d_out, int out_size)
{
    const float* x     = (const float*)d_in[0];
    const float* times = (const float*)d_in[1];
    const float* mask  = (const float*)d_in[2];
    const float* query = (const float*)d_in[3];
    const float* w_lin = (const float*)d_in[4];
    const float* b_lin = (const float*)d_in[5];
    const float* w_per = (const float*)d_in[6];
    const float* b_per = (const float*)d_in[7];
    const float* Wq    = (const float*)d_in[8];
    const float* bq    = (const float*)d_in[9];
    const float* Wk    = (const float*)d_in[10];
    const float* bk    = (const float*)d_in[11];
    const float* Wo    = (const float*)d_in[12];
    const float* bo    = (const float*)d_in[13];
    const float* W_ih  = (const float*)d_in[14];
    const float* b_ih  = (const float*)d_in[15];
    const float* W_hh  = (const float*)d_in[16];
    const float* b_hh  = (const float*)d_in[17];
    const float* r1_w  = (const float*)d_in[18];
    const float* r1_b  = (const float*)d_in[19];
    const float* r2_w  = (const float*)d_in[20];
    const float* r2_b  = (const float*)d_in[21];
    const float* r3_w  = (const float*)d_in[22];
    const float* r3_b  = (const float*)d_in[23];
    const float* r4_w  = (const float*)d_in[24];
    const float* r4_b  = (const float*)d_in[25];
    float* out = (float*)d_out;

    embed_proj_kernel<<<130, 256>>>(times, query, w_lin, b_lin, w_per, b_per,
                                    Wk, bk, Wq, bq);

    const int ATTN_SMEM = (512 + 4096) * 4 + 256 * 32 * 8; // 83968 B
    cudaFuncSetAttribute(attn_kernel,
                         cudaFuncAttributeMaxDynamicSharedMemorySize, ATTN_SMEM);
    attn_kernel<<<dim3(4, 4, 16), 512, ATTN_SMEM>>>(x, mask);

    combine_w_kernel<<<17, 256>>>(Wo, bo, W_ih, b_ih, b_hh);

    pre_kernel<<<64, 256>>>();

    rnn_regr_kernel<<<16, 512>>>(W_hh, r1_w, r1_b, r2_w, r2_b,
                                 r3_w, r3_b, r4_w, r4_b, out);
}

// round 3
// speedup vs baseline: 1.8920x; 1.3011x over previous
#include <cuda_runtime.h>
#include <cuda_bf16.h>
#include <math.h>

// Problem constants
#define B_   16
#define L_   256
#define LQ_  64
#define ET_  128
#define H_   4
#define ETK_ 32
#define DIM_ 64
#define D_IN_ 32
#define IE_  8

// ---------------- scratch (device globals; no allocation) ----------------
__device__ float g_q[H_ * LQ_ * ETK_];          // (h, q, e)  pre-scaled by 1/sqrt(32)
__device__ float g_k[B_ * H_ * L_ * ETK_];      // (b, h, l, e)
__device__ float g_att[B_ * LQ_ * ET_];         // (b, q, h*32+d)  compact (ones folded)
__device__ float g_Wc[ET_ * ET_];               // 128 x 128 : compact rows of Wo @ W_ih
__device__ float g_bc[ET_];                     // combined bias (incl. ones-rows fold)
__device__ float g_pre[B_ * LQ_ * ET_];         // (b, t, j)

// ======================================================================
// Kernel 1 (fused): time-embed + Q/K projections  AND  Wc/bc combine.
//   blocks 0..255   : K rows   (16 rows each)
//   blocks 256..259 : Q rows   (16 rows each)
//   blocks 260..267 : Wc compact tiles (16 rows each)
//   block  268      : combined bias
// 256 threads; dynamic smem = 16*128 + 128*128 floats = 73728 B.
// ======================================================================
__global__ void stage1_kernel(
    const float* __restrict__ times, const float* __restrict__ query,
    const float* __restrict__ w_lin, const float* __restrict__ b_lin,
    const float* __restrict__ w_per, const float* __restrict__ b_per,
    const float* __restrict__ Wk, const float* __restrict__ bk,
    const float* __restrict__ Wq, const float* __restrict__ bq,
    const float* __restrict__ Wo, const float* __restrict__ bo,
    const float* __restrict__ W_ih, const float* __restrict__ b_ih,
    const float* __restrict__ b_hh)
{
    extern __shared__ float sm[];
    float* s_a = sm;              // 16 x 128
    float* s_w = sm + 16 * 128;   // 128 x 128
    __shared__ float tv[16];

    const int tid = threadIdx.x;
    const int bx  = blockIdx.x;
    const int tx = tid & 31;      // col group (4 cols)
    const int ty = tid >> 5;      // row group (2 rows)

    if (bx < 260) {
        // ---------------- embedding + projection ----------------
        const bool is_q = (bx >= 256);
        const int r0 = bx * 16;
        if (tid < 16) tv[tid] = is_q ? query[r0 - 4096 + tid] : times[r0 + tid];
        __syncthreads();

        const float wl = w_lin[0], bl = b_lin[0];
        for (int idx = tid; idx < 16 * 128; idx += 256) {
            int r = idx >> 7, c = idx & 127;
            float t = tv[r];
            s_a[idx] = (c == 0) ? fmaf(t, wl, bl)
                                : __sinf(fmaf(t, w_per[c - 1], b_per[c - 1]));
        }
        const float* W    = is_q ? Wq : Wk;
        const float* bias = is_q ? bq : bk;
#pragma unroll
        for (int idx = tid * 4; idx < 128 * 128; idx += 1024)
            *(float4*)(s_w + idx) = *(const float4*)(W + idx);
        __syncthreads();

        float acc[2][4];
#pragma unroll
        for (int r = 0; r < 2; r++)
#pragma unroll
            for (int c = 0; c < 4; c++) acc[r][c] = 0.f;

#pragma unroll 4
        for (int i = 0; i < 128; i++) {
            float4 w = *(const float4*)(s_w + i * 128 + 4 * tx);
            float e0 = s_a[(2 * ty) * 128 + i];
            float e1 = s_a[(2 * ty + 1) * 128 + i];
            acc[0][0] = fmaf(e0, w.x, acc[0][0]); acc[0][1] = fmaf(e0, w.y, acc[0][1]);
            acc[0][2] = fmaf(e0, w.z, acc[0][2]); acc[0][3] = fmaf(e0, w.w, acc[0][3]);
            acc[1][0] = fmaf(e1, w.x, acc[1][0]); acc[1][1] = fmaf(e1, w.y, acc[1][1]);
            acc[1][2] = fmaf(e1, w.z, acc[1][2]); acc[1][3] = fmaf(e1, w.w, acc[1][3]);
        }

        const float scale = is_q ? 0.17677669529663687f : 1.0f;
#pragma unroll
        for (int r = 0; r < 2; r++) {
            int grow = r0 + 2 * ty + r;
#pragma unroll
            for (int c = 0; c < 4; c++) {
                int col = 4 * tx + c;
                float v = (acc[r][c] + bias[col]) * scale;
                int h = col >> 5, e = col & 31;
                if (is_q) g_q[(h * LQ_ + (grow - 4096)) * ETK_ + e] = v;
                else {
                    int b = grow >> 8, l = grow & 255;
                    g_k[((b * H_ + h) * L_ + l) * ETK_ + e] = v;
                }
            }
        }
    } else if (bx < 268) {
        // ---------------- Wc compact tile:  Wc[cr] = Wo[map(cr)] @ W_ih ----------------
        const int cr0 = (bx - 260) * 16;
        for (int idx = tid; idx < 16 * 128; idx += 256) {
            int rr = idx >> 7, c = idx & 127;
            int cr = cr0 + rr;
            int r = (cr >> 5) * 64 + (cr & 31);   // d<32 rows of Wo
            s_a[idx] = Wo[r * 128 + c];
        }
#pragma unroll
        for (int idx = tid * 4; idx < 128 * 128; idx += 1024)
            *(float4*)(s_w + idx) = *(const float4*)(W_ih + idx);
        __syncthreads();

        float acc[2][4];
#pragma unroll
        for (int r = 0; r < 2; r++)
#pragma unroll
            for (int c = 0; c < 4; c++) acc[r][c] = 0.f;

#pragma unroll 4
        for (int i = 0; i < 128; i++) {
            float4 w = *(const float4*)(s_w + i * 128 + 4 * tx);
            float e0 = s_a[(2 * ty) * 128 + i];
            float e1 = s_a[(2 * ty + 1) * 128 + i];
            acc[0][0] = fmaf(e0, w.x, acc[0][0]); acc[0][1] = fmaf(e0, w.y, acc[0][1]);
            acc[0][2] = fmaf(e0, w.z, acc[0][2]); acc[0][3] = fmaf(e0, w.w, acc[0][3]);
            acc[1][0] = fmaf(e1, w.x, acc[1][0]); acc[1][1] = fmaf(e1, w.y, acc[1][1]);
            acc[1][2] = fmaf(e1, w.z, acc[1][2]); acc[1][3] = fmaf(e1, w.w, acc[1][3]);
        }
#pragma unroll
        for (int r = 0; r < 2; r++)
#pragma unroll
            for (int c = 0; c < 4; c++)
                g_Wc[(cr0 + 2 * ty + r) * 128 + 4 * tx + c] = acc[r][c];
    } else {
        // ---------------- bias:  bc = (bo + sum_ones Wo[r]) @ W_ih + b_ih + b_hh ----------------
        const int j = tid & 127, hf = tid >> 7;
        float accv = 0.f;
#pragma unroll 4
        for (int i = 0; i < 64; i++) {
            int oi = hf * 64 + i;
            int r = (oi >> 5) * 64 + 32 + (oi & 31);  // d>=32 "ones" rows
            accv += Wo[r * 128 + j];
        }
        s_a[hf * 128 + j] = accv;
        __syncthreads();
        float v = 0.f;
        if (tid < 128) v = bo[tid] + s_a[tid] + s_a[128 + tid];
        __syncthreads();
        if (tid < 128) s_a[tid] = v;
#pragma unroll
        for (int idx = tid * 4; idx < 128 * 128; idx += 1024)
            *(float4*)(s_w + idx) = *(const float4*)(W_ih + idx);
        __syncthreads();
        if (tid < 128) {
            float acc = b_ih[tid] + b_hh[tid];
#pragma unroll 8
            for (int i = 0; i < 128; i++)
                acc = fmaf(s_a[i], s_w[i * 128 + tid], acc);
            g_bc[tid] = acc;
        }
    }
}

// ======================================================================
// Kernel 2: masked per-feature attention (compact output, ones folded away).
// grid (qt=4, h=4, b=16), 512 threads, dynamic smem = 83968 B.
// ======================================================================
__global__ void attn_kernel(const float* __restrict__ x,
                            const float* __restrict__ mask)
{
    extern __shared__ float smem[];
    float*  qv  = smem;                         // 16*32
    float*  s_s = smem + 512;                   // 16*256
    float2* mxm = (float2*)(smem + 512 + 4096); // 256*32

    const int tid = threadIdx.x;
    const int qt = blockIdx.x, h = blockIdx.y, b = blockIdx.z;

    qv[tid] = g_q[(h * LQ_ + qt * 16) * ETK_ + tid];

    const float* xb = x    + b * L_ * D_IN_;
    const float* mb = mask + b * L_ * D_IN_;
    for (int idx = tid; idx < L_ * D_IN_; idx += 512) {
        float m = mb[idx];
        mxm[idx] = make_float2(m * xb[idx], m);
    }
    __syncthreads();

    // scores (q pre-scaled by 1/sqrt(32))
    {
        const int k  = tid & 255;
        const int qh = tid >> 8;
        const float* kp = g_k + ((b * H_ + h) * L_ + k) * ETK_;
        float kv[32];
#pragma unroll
        for (int i = 0; i < 8; i++) {
            float4 v = *(const float4*)(kp + 4 * i);
            kv[4 * i] = v.x; kv[4 * i + 1] = v.y; kv[4 * i + 2] = v.z; kv[4 * i + 3] = v.w;
        }
#pragma unroll
        for (int qq = 0; qq < 8; qq++) {
            int q = qh * 8 + qq;
            float acc = 0.f;
#pragma unroll
            for (int e = 0; e < 32; e++) acc = fmaf(qv[q * 32 + e], kv[e], acc);
            s_s[q * 256 + k] = acc;
        }
    }
    __syncthreads();

    // row max + exp
    {
        const int wq = tid >> 5, lane = tid & 31;
        float vals[8], m = -1e30f;
#pragma unroll
        for (int i = 0; i < 8; i++) {
            vals[i] = s_s[wq * 256 + lane + 32 * i];
            m = fmaxf(m, vals[i]);
        }
#pragma unroll
        for (int off = 16; off; off >>= 1)
            m = fmaxf(m, __shfl_xor_sync(0xffffffffu, m, off));
#pragma unroll
        for (int i = 0; i < 8; i++)
            s_s[wq * 256 + lane + 32 * i] = __expf(vals[i] - m);
    }
    __syncthreads();

    // num/den
    {
        const int q = tid >> 5, d = tid & 31;
        float num = 0.f, den = 0.f;
        const float* ep = s_s + q * 256;
        const float2* vp = mxm + d;
#pragma unroll 4
        for (int k = 0; k < 256; k++) {
            float  e = ep[k];
            float2 v = vp[k * 32];
            num = fmaf(e, v.x, num);
            den = fmaf(e, v.y, den);
        }
        float att = (den > 0.f) ? (num / den) : 0.f;
        g_att[(b * LQ_ + qt * 16 + q) * ET_ + h * ETK_ + d] = att;
    }
}

// ======================================================================
// Kernel 3: pre = att_c @ Wc + bc   (1024 x 128, K=128)
// grid (cc=4, rt=64), 256 threads; whole W column-slice staged once.
// ======================================================================
__global__ void pre_kernel()
{
    __shared__ float a_s[16 * 128];
    __shared__ float w_s[128 * 32];

    const int tid = threadIdx.x;
    const int cc = blockIdx.x;
    const int r0 = blockIdx.y * 16;

#pragma unroll
    for (int idx = tid * 4; idx < 16 * 128; idx += 1024)
        *(float4*)(a_s + idx) = *(const float4*)(g_att + r0 * 128 + idx);

#pragma unroll
    for (int f = tid * 4; f < 128 * 32; f += 1024) {
        int i = f >> 5, c = f & 31;
        *(float4*)(w_s + f) = *(const float4*)(g_Wc + i * 128 + cc * 32 + c);
    }
    __syncthreads();

    const int tx = tid & 31;
    const int ty = tid >> 5;

    float a0 = 0.f, a1 = 0.f;
#pragma unroll 8
    for (int i = 0; i < 128; i++) {
        float w = w_s[i * 32 + tx];
        a0 = fmaf(a_s[(2 * ty) * 128 + i],     w, a0);
        a1 = fmaf(a_s[(2 * ty + 1) * 128 + i], w, a1);
    }

    const int col = cc * 32 + tx;
    const float bias = g_bc[col];
    g_pre[(r0 + 2 * ty) * 128 + col]     = a0 + bias;
    g_pre[(r0 + 2 * ty + 1) * 128 + col] = a1 + bias;
}

// ======================================================================
// Kernel 4: RNN (64 sequential steps) + regressor, fused. grid 16 x 512.
// tanh via exp identity (fast MUFU path). Next pre row prefetched.
// ======================================================================
__device__ __forceinline__ float fast_tanh(float z)
{
    float e2 = __expf(2.f * z);
    return 1.f - __fdividef(2.f, e2 + 1.f);
}

__device__ __forceinline__ void matvec128(const float* in_s, float* out_s,
                                          const float* __restrict__ Wg,
                                          const float* __restrict__ bg,
                                          int s, int j, int tid,
                                          float part[4][128])
{
    float a0 = 0.f, a1 = 0.f;
    const float* wp = Wg + (32 * s) * 128 + j;
#pragma unroll
    for (int i = 0; i < 32; i += 2) {
        a0 = fmaf(in_s[32 * s + i],     wp[i * 128],       a0);
        a1 = fmaf(in_s[32 * s + i + 1], wp[(i + 1) * 128], a1);
    }
    part[s][j] = a0 + a1;
    __syncthreads();
    if (tid < 128)
        out_s[tid] = bg[tid] + ((part[0][tid] + part[1][tid]) +
                                (part[2][tid] + part[3][tid]));
    __syncthreads();
}

__global__ void rnn_regr_kernel(const float* __restrict__ W_hh,
                                const float* __restrict__ r1_w, const float* __restrict__ r1_b,
                                const float* __restrict__ r2_w, const float* __restrict__ r2_b,
                                const float* __restrict__ r3_w, const float* __restrict__ r3_b,
                                const float* __restrict__ r4_w, const float* __restrict__ r4_b,
                                float* __restrict__ out)
{
    __shared__ float h_s[128];
    __shared__ float v_s[128];
    __shared__ float part[4][128];

    const int tid = threadIdx.x;
    const int j = tid & 127;
    const int s = tid >> 7;

    float w[32];
#pragma unroll
    for (int i = 0; i < 32; i++) w[i] = W_hh[(32 * s + i) * 128 + j];

    if (tid < 128) h_s[tid] = 0.f;
    __syncthreads();

    const float* pre_b = g_pre + blockIdx.x * LQ_ * ET_;
    float pre_cur = (tid < 128) ? pre_b[tid] : 0.f;

    for (int step = 0; step < LQ_; step++) {
        float pre_nxt = 0.f;
        if (tid < 128 && step + 1 < LQ_) pre_nxt = pre_b[(step + 1) * 128 + tid];

        float a0 = 0.f, a1 = 0.f, a2 = 0.f, a3 = 0.f;
#pragma unroll
        for (int i = 0; i < 32; i += 4) {
            a0 = fmaf(h_s[32 * s + i],     w[i],     a0);
            a1 = fmaf(h_s[32 * s + i + 1], w[i + 1], a1);
            a2 = fmaf(h_s[32 * s + i + 2], w[i + 2], a2);
            a3 = fmaf(h_s[32 * s + i + 3], w[i + 3], a3);
        }
        part[s][j] = (a0 + a1) + (a2 + a3);
        __syncthreads();
        if (tid < 128) {
            h_s[tid] = fast_tanh(pre_cur +
                                 ((part[0][tid] + part[1][tid]) +
                                  (part[2][tid] + part[3][tid])));
        }
        __syncthreads();
        pre_cur = pre_nxt;
    }

    matvec128(h_s, v_s, r1_w, r1_b, s, j, tid, part);
    matvec128(v_s, h_s, r2_w, r2_b, s, j, tid, part);
    matvec128(h_s, v_s, r3_w, r3_b, s, j, tid, part);

    if (tid < 256) {
        int o = tid >> 5, lane = tid & 31;
        float acc = 0.f;
#pragma unroll
        for (int ii = 0; ii < 4; ii++) {
            int i = lane * 4 + ii;
            acc = fmaf(v_s[i], r4_w[i * 8 + o], acc);
        }
#pragma unroll
        for (int off = 16; off; off >>= 1)
            acc += __shfl_xor_sync(0xffffffffu, acc, off);
        if (lane == 0) out[blockIdx.x * 8 + o] = acc + r4_b[o];
    }
}

// ======================================================================
extern "C" void kernel_launch(void* const* d_in, const int* in_sizes, int n_in,
                              void* d_out, int out_size)
{
    const float* x     = (const float*)d_in[0];
    const float* times = (const float*)d_in[1];
    const float* mask  = (const float*)d_in[2];
    const float* query = (const float*)d_in[3];
    const float* w_lin = (const float*)d_in[4];
    const float* b_lin = (const float*)d_in[5];
    const float* w_per = (const float*)d_in[6];
    const float* b_per = (const float*)d_in[7];
    const float* Wq    = (const float*)d_in[8];
    const float* bq    = (const float*)d_in[9];
    const float* Wk    = (const float*)d_in[10];
    const float* bk    = (const float*)d_in[11];
    const float* Wo    = (const float*)d_in[12];
    const float* bo    = (const float*)d_in[13];
    const float* W_ih  = (const float*)d_in[14];
    const float* b_ih  = (const float*)d_in[15];
    const float* W_hh  = (const float*)d_in[16];
    const float* b_hh  = (const float*)d_in[17];
    const float* r1_w  = (const float*)d_in[18];
    const float* r1_b  = (const float*)d_in[19];
    const float* r2_w  = (const float*)d_in[20];
    const float* r2_b  = (const float*)d_in[21];
    const float* r3_w  = (const float*)d_in[22];
    const float* r3_b  = (const float*)d_in[23];
    const float* r4_w  = (const float*)d_in[24];
    const float* r4_b  = (const float*)d_in[25];
    float* out = (float*)d_out;

    const int S1_SMEM = (16 * 128 + 128 * 128) * 4;  // 73728
    cudaFuncSetAttribute(stage1_kernel,
                         cudaFuncAttributeMaxDynamicSharedMemorySize, S1_SMEM);
    stage1_kernel<<<269, 256, S1_SMEM>>>(times, query, w_lin, b_lin, w_per, b_per,
                                         Wk, bk, Wq, bq, Wo, bo, W_ih, b_ih, b_hh);

    const int ATTN_SMEM = (512 + 4096) * 4 + 256 * 32 * 8;  // 83968
    cudaFuncSetAttribute(attn_kernel,
                         cudaFuncAttributeMaxDynamicSharedMemorySize, ATTN_SMEM);
    attn_kernel<<<dim3(4, 4, 16), 512, ATTN_SMEM>>>(x, mask);

    pre_kernel<<<dim3(4, 64), 256>>>();

    rnn_regr_kernel<<<16, 512>>>(W_hh, r1_w, r1_b, r2_w, r2_b,
                                 r3_w, r3_b, r4_w, r4_b, out);
}